// round 11
// baseline (speedup 1.0000x reference)
#include <cuda_runtime.h>
#include <cuda_fp16.h>
#include <cstdint>
#include <math.h>

// Problem constants
#define NUM_TOK 8192
#define DIM     1024
#define NEXP    8
#define FFN     4096

// GEMM tiling (fp16): CTA 128x256, warp tile 64x64, K-tile 64 halves (128B/row)
#define BM 128
#define BN 256
#define BKF 64
#define NSTAGE 3
#define MAX_SLOTS (2*NUM_TOK + NEXP*BM)     // 17408
#define MAX_MTILES (MAX_SLOTS/BM)           // 136

#define A_TILE_BYTES 16384                  // 128 rows x 128 B
#define B_TILE_BYTES 32768                  // 256 rows x 128 B
#define STAGE_BYTES (A_TILE_BYTES + B_TILE_BYTES)   // 48 KB
#define SMEM_TOTAL (NSTAGE*STAGE_BYTES + 128)       // ~144 KB -> 1 CTA/SM

// ---------------- device scratch ----------------
__device__ int    g_counts[NEXP];
__device__ int    g_fill[NEXP];
__device__ int    g_off[NEXP+1];
__device__ int    g_flag;
__device__ int    g_tok_e[2*NUM_TOK];
__device__ float  g_tok_w[2*NUM_TOK];
__device__ int    g_tok_slot[2*NUM_TOK];
__device__ int    g_slot_tok[MAX_SLOTS];
__device__ float  g_slot_w[MAX_SLOTS];
__device__ __half g_xh[(size_t)NUM_TOK * DIM];
__device__ __half g_w1h[(size_t)NEXP * FFN * DIM];
__device__ __half g_w2h[(size_t)NEXP * DIM * FFN];
__device__ __half g_hh[(size_t)MAX_SLOTS * FFN];
__device__ float  g_ho[(size_t)MAX_SLOTS * DIM];

// ---------------- helpers ----------------
__device__ __forceinline__ float gelu_exact(float v) {
    return 0.5f * v * (1.0f + erff(v * 0.70710678118654752f));
}
__device__ __forceinline__ uint32_t smem_u32(const void* p) {
    uint32_t a;
    asm("{ .reg .u64 t; cvta.to.shared.u64 t, %1; cvt.u32.u64 %0, t; }" : "=r"(a) : "l"(p));
    return a;
}
__device__ __forceinline__ void mma_f16(float c[4], const uint32_t a[4], const uint32_t b[2]) {
    asm volatile(
        "mma.sync.aligned.m16n8k16.row.col.f32.f16.f16.f32 "
        "{%0,%1,%2,%3},{%4,%5,%6,%7},{%8,%9},{%0,%1,%2,%3};"
        : "+f"(c[0]), "+f"(c[1]), "+f"(c[2]), "+f"(c[3])
        : "r"(a[0]), "r"(a[1]), "r"(a[2]), "r"(a[3]), "r"(b[0]), "r"(b[1]));
}
__device__ __forceinline__ void ldsm4(uint32_t& r0, uint32_t& r1, uint32_t& r2, uint32_t& r3,
                                      uint32_t addr) {
    asm volatile("ldmatrix.sync.aligned.m8n8.x4.shared.b16 {%0,%1,%2,%3}, [%4];"
                 : "=r"(r0), "=r"(r1), "=r"(r2), "=r"(r3) : "r"(addr));
}
__device__ __forceinline__ void cpa16(uint32_t dst, const void* src, int srcbytes) {
    asm volatile("cp.async.cg.shared.global [%0], [%1], 16, %2;"
                 :: "r"(dst), "l"(src), "r"(srcbytes) : "memory");
}
__device__ __forceinline__ void cpa_commit() { asm volatile("cp.async.commit_group;" ::: "memory"); }
__device__ __forceinline__ void cpa_wait1()  { asm volatile("cp.async.wait_group 1;" ::: "memory"); }

// ---------------- prep: reset counters + fp32->fp16 of x, w1, w2 ----------------
__global__ void prep_kernel(const float4* __restrict__ x, const float4* __restrict__ w1,
                            const float4* __restrict__ w2) {
    const int n8x  = NUM_TOK * DIM / 8;
    const int n8w1 = NEXP * FFN * DIM / 8;
    int i = blockIdx.x * blockDim.x + threadIdx.x;
    if (i < NEXP) { g_counts[i] = 0; g_fill[i] = 0; }
    if (i == NEXP) g_flag = 0;

    const float4* src;
    __half* dst;
    int j = i;
    if (j < n8x) { src = x; dst = g_xh; }
    else if (j < n8x + n8w1) { j -= n8x; src = w1; dst = g_w1h; }
    else { j -= n8x + n8w1; src = w2; dst = g_w2h; }

    float4 v0 = src[2 * j], v1 = src[2 * j + 1];
    __half2 h0 = __floats2half2_rn(v0.x, v0.y);
    __half2 h1 = __floats2half2_rn(v0.z, v0.w);
    __half2 h2 = __floats2half2_rn(v1.x, v1.y);
    __half2 h3 = __floats2half2_rn(v1.z, v1.w);
    uint4 o;
    o.x = *(uint32_t*)&h0; o.y = *(uint32_t*)&h1;
    o.z = *(uint32_t*)&h2; o.w = *(uint32_t*)&h3;
    ((uint4*)dst)[j] = o;
}

// ---------------- router ----------------
__global__ void router_kernel(const float* __restrict__ x, const float* __restrict__ rw) {
    int warp = threadIdx.x >> 5, lane = threadIdx.x & 31;
    int t = blockIdx.x * 8 + warp;
    float acc[NEXP];
#pragma unroll
    for (int e = 0; e < NEXP; e++) acc[e] = 0.0f;
    const float* xp = x + (size_t)t * DIM;
    for (int k = lane; k < DIM; k += 32) {
        float xv = xp[k];
#pragma unroll
        for (int e = 0; e < NEXP; e++) acc[e] += xv * rw[e * DIM + k];
    }
#pragma unroll
    for (int e = 0; e < NEXP; e++) {
#pragma unroll
        for (int o = 16; o > 0; o >>= 1) acc[e] += __shfl_xor_sync(0xffffffffu, acc[e], o);
    }
    if (lane == 0) {
        int be = 0; float bv = acc[0];
#pragma unroll
        for (int e = 1; e < NEXP; e++) if (acc[e] > bv) { bv = acc[e]; be = e; }
        int be2 = -1; float bv2 = -1e30f;
#pragma unroll
        for (int e = 0; e < NEXP; e++) if (e != be && acc[e] > bv2) { bv2 = acc[e]; be2 = e; }
        float p0 = 1.0f / (1.0f + expf(bv2 - bv));
        g_tok_e[2 * t] = be;  g_tok_e[2 * t + 1] = be2;
        g_tok_w[2 * t] = p0;  g_tok_w[2 * t + 1] = 1.0f - p0;
        atomicAdd(&g_counts[be], 1);
        atomicAdd(&g_counts[be2], 1);
    }
}

// ---------------- place (offsets fused via device-flag spin; 32 resident blocks) ----------------
__global__ void place_kernel() {
    int flat = blockIdx.x * blockDim.x + threadIdx.x;
    if (flat == 0) {
        int o = 0;
        for (int e = 0; e < NEXP; e++) {
            g_off[e] = o;
            o += ((g_counts[e] + BM - 1) / BM) * BM;
        }
        g_off[NEXP] = o;
        __threadfence();
        atomicExch(&g_flag, 1);
    }
    while (atomicAdd(&g_flag, 0) == 0) {}
    __threadfence();

    if (flat < NEXP * BM) {
        int e = flat / BM, j = flat % BM;
        int idx = g_off[e] + g_counts[e] + j;
        if (idx < g_off[e + 1]) { g_slot_tok[idx] = -1; g_slot_w[idx] = 0.0f; }
    }
    int t = flat;
    if (t < NUM_TOK) {
#pragma unroll
        for (int k = 0; k < 2; k++) {
            int e = g_tok_e[2 * t + k];
            int p = atomicAdd(&g_fill[e], 1);
            int idx = g_off[e] + p;
            g_slot_tok[idx] = t;
            g_slot_w[idx] = g_tok_w[2 * t + k];
            g_tok_slot[2 * t + k] = idx;
        }
    }
}

// ---------------- combine: out[t] = ho[slot0(t)] + ho[slot1(t)] ----------------
__global__ void combine_kernel(float4* __restrict__ out) {
    const int D4 = DIM / 4;
    int i = blockIdx.x * blockDim.x + threadIdx.x;
    if (i >= NUM_TOK * D4) return;
    int t = i / D4, d = i % D4;
    const float4* h0 = (const float4*)(g_ho + (size_t)g_tok_slot[2 * t] * DIM);
    const float4* h1 = (const float4*)(g_ho + (size_t)g_tok_slot[2 * t + 1] * DIM);
    float4 a = h0[d], b = h1[d];
    out[i] = make_float4(a.x + b.x, a.y + b.y, a.z + b.z, a.w + b.w);
}

// ================= fp16 pipelined GEMM core (64x64 warp tiles) =================
struct Pre {
    uint32_t rowA[4];   // (wm + mt*16 + rlA)*128, relative to A tile base
    uint32_t rowB[4];   // A_TILE_BYTES + (wn + q*16 + nlB)*128
    uint32_t offA[4];   // ((ks*2 + selA) ^ rlA7) << 4
    uint32_t offB[4];   // ((ks*2 + selB) ^ nlB7) << 4
};

__device__ __forceinline__ void pre_init(Pre& p, int tid) {
    int warp = (tid >> 5) & 7, lane = tid & 31;
    int wm = (warp & 1) * 64, wn = (warp >> 1) * 64;
    int rlA = lane & 15, selA = lane >> 4, rlA7 = rlA & 7;
    int nlB = ((lane >> 4) << 3) + (lane & 7);
    int selB = (lane >> 3) & 1, nlB7 = nlB & 7;
#pragma unroll
    for (int mt = 0; mt < 4; mt++) p.rowA[mt] = (uint32_t)(wm + mt * 16 + rlA) * 128;
#pragma unroll
    for (int q = 0; q < 4; q++)   p.rowB[q] = A_TILE_BYTES + (uint32_t)(wn + q * 16 + nlB) * 128;
#pragma unroll
    for (int ks = 0; ks < 4; ks++) {
        p.offA[ks] = ((uint32_t)((ks * 2 + selA) ^ rlA7)) << 4;
        p.offB[ks] = ((uint32_t)((ks * 2 + selB) ^ nlB7)) << 4;
    }
}

// 64x64 warp tile: 4 mt x 8 nt accumulators, 4 A-ldsm + 4 B-ldsm per ks-step.
__device__ __forceinline__ void compute_tile(const Pre& p, uint32_t base, float c[4][8][4]) {
#pragma unroll
    for (int ks = 0; ks < 4; ks++) {
        uint32_t a[4][4], b[8][2];
#pragma unroll
        for (int mt = 0; mt < 4; mt++)
            ldsm4(a[mt][0], a[mt][1], a[mt][2], a[mt][3], base + p.rowA[mt] + p.offA[ks]);
#pragma unroll
        for (int q = 0; q < 4; q++)
            ldsm4(b[2*q][0], b[2*q][1], b[2*q+1][0], b[2*q+1][1], base + p.rowB[q] + p.offB[ks]);
#pragma unroll
        for (int mt = 0; mt < 4; mt++)
#pragma unroll
            for (int nt = 0; nt < 8; nt++)
                mma_f16(c[mt][nt], a[mt], b[nt]);
    }
}

// ---------------- GEMM1: h = gelu(x_gather @ W1^T) ----------------
__global__ void __launch_bounds__(256, 1)
gemm1_p() {
    extern __shared__ char smem[];
    __shared__ int stok[BM];

    const int tid = threadIdx.x;
    const int m0 = blockIdx.x * BM;
    if (m0 >= g_off[NEXP]) return;
    int e = 0;
    while (m0 >= g_off[e + 1]) e++;
    const __half* w1e = g_w1h + (size_t)e * FFN * DIM;
    const int n0 = blockIdx.y * BN;

    if (tid < BM) stok[tid] = g_slot_tok[m0 + tid];
    __syncthreads();

    uint32_t sb = (smem_u32(smem) + 127u) & ~127u;

    // loader: thread covers rows row0 + 32*i (A: i<4, B: i<8), fixed chunk ch
    const int row0 = tid >> 3, ch = tid & 7;
    const uint32_t dsto0 = (uint32_t)row0 * 128 + ((uint32_t)(ch ^ (row0 & 7)) << 4);
    const __half* asrc[4]; int asz[4];
#pragma unroll
    for (int i = 0; i < 4; i++) {
        int tok = stok[row0 + 32 * i];
        asz[i]  = (tok < 0) ? 0 : 16;
        asrc[i] = g_xh + (size_t)((tok < 0) ? 0 : tok) * DIM + ch * 8;
    }
    const __half* bsrc0 = w1e + (size_t)(n0 + row0) * DIM + ch * 8;

    Pre pre; pre_init(pre, tid);

    float c[4][8][4];
#pragma unroll
    for (int i = 0; i < 4; i++)
#pragma unroll
        for (int j = 0; j < 8; j++)
#pragma unroll
            for (int k = 0; k < 4; k++) c[i][j][k] = 0.0f;

    const int NK = DIM / BKF;   // 16
#pragma unroll
    for (int s = 0; s < 2; s++) {
        uint32_t ab = sb + s * STAGE_BYTES, bb = ab + A_TILE_BYTES;
#pragma unroll
        for (int i = 0; i < 4; i++)
            cpa16(ab + dsto0 + i * 4096, asrc[i] + s * BKF, asz[i]);
#pragma unroll
        for (int i = 0; i < 8; i++)
            cpa16(bb + dsto0 + i * 4096, bsrc0 + (size_t)i * 32 * DIM + s * BKF, 16);
        cpa_commit();
    }

    for (int kt = 0; kt < NK; kt++) {
        int s = kt % NSTAGE;
        cpa_wait1();
        __syncthreads();
        if (kt + 2 < NK) {
            int sn = (kt + 2) % NSTAGE;
            uint32_t ab = sb + sn * STAGE_BYTES, bb = ab + A_TILE_BYTES;
            int k0 = (kt + 2) * BKF;
#pragma unroll
            for (int i = 0; i < 4; i++)
                cpa16(ab + dsto0 + i * 4096, asrc[i] + k0, asz[i]);
#pragma unroll
            for (int i = 0; i < 8; i++)
                cpa16(bb + dsto0 + i * 4096, bsrc0 + (size_t)i * 32 * DIM + k0, 16);
        }
        cpa_commit();
        compute_tile(pre, sb + s * STAGE_BYTES, c);
    }

    // epilogue: gelu -> fp16 h
    int lane = tid & 31, warp = (tid >> 5) & 7;
    int wm = (warp & 1) * 64, wn = (warp >> 1) * 64;
    int g = lane >> 2, tg = lane & 3;
#pragma unroll
    for (int mt = 0; mt < 4; mt++) {
#pragma unroll
        for (int nt = 0; nt < 8; nt++) {
            int mb = m0 + wm + mt * 16 + g;
            int nb = n0 + wn + nt * 8 + tg * 2;
            __half2 v0 = __floats2half2_rn(gelu_exact(c[mt][nt][0]), gelu_exact(c[mt][nt][1]));
            __half2 v1 = __floats2half2_rn(gelu_exact(c[mt][nt][2]), gelu_exact(c[mt][nt][3]));
            *(__half2*)(g_hh + (size_t)mb * FFN + nb) = v0;
            *(__half2*)(g_hh + (size_t)(mb + 8) * FFN + nb) = v1;
        }
    }
}

// ---------------- GEMM2: ho[slot] = w_slot * (h[slot] @ W2^T), non-atomic ----------------
__global__ void __launch_bounds__(256, 1)
gemm2_p() {
    extern __shared__ char smem[];
    __shared__ float swv[BM];

    const int tid = threadIdx.x;
    const int m0 = blockIdx.x * BM;
    if (m0 >= g_off[NEXP]) return;
    int e = 0;
    while (m0 >= g_off[e + 1]) e++;
    const __half* w2e = g_w2h + (size_t)e * DIM * FFN;
    const int n0 = blockIdx.y * BN;

    if (tid < BM) swv[tid] = g_slot_w[m0 + tid];
    __syncthreads();

    uint32_t sb = (smem_u32(smem) + 127u) & ~127u;

    const int row0 = tid >> 3, ch = tid & 7;
    const uint32_t dsto0 = (uint32_t)row0 * 128 + ((uint32_t)(ch ^ (row0 & 7)) << 4);
    const __half* asrc0 = g_hh + (size_t)(m0 + row0) * FFN + ch * 8;
    const __half* bsrc0 = w2e + (size_t)(n0 + row0) * FFN + ch * 8;

    Pre pre; pre_init(pre, tid);

    float c[4][8][4];
#pragma unroll
    for (int i = 0; i < 4; i++)
#pragma unroll
        for (int j = 0; j < 8; j++)
#pragma unroll
            for (int k = 0; k < 4; k++) c[i][j][k] = 0.0f;

    const int NK = FFN / BKF;   // 64
#pragma unroll
    for (int s = 0; s < 2; s++) {
        uint32_t ab = sb + s * STAGE_BYTES, bb = ab + A_TILE_BYTES;
#pragma unroll
        for (int i = 0; i < 4; i++)
            cpa16(ab + dsto0 + i * 4096, asrc0 + (size_t)i * 32 * FFN + s * BKF, 16);
#pragma unroll
        for (int i = 0; i < 8; i++)
            cpa16(bb + dsto0 + i * 4096, bsrc0 + (size_t)i * 32 * FFN + s * BKF, 16);
        cpa_commit();
    }

    for (int kt = 0; kt < NK; kt++) {
        int s = kt % NSTAGE;
        cpa_wait1();
        __syncthreads();
        if (kt + 2 < NK) {
            int sn = (kt + 2) % NSTAGE;
            uint32_t ab = sb + sn * STAGE_BYTES, bb = ab + A_TILE_BYTES;
            int k0 = (kt + 2) * BKF;
#pragma unroll
            for (int i = 0; i < 4; i++)
                cpa16(ab + dsto0 + i * 4096, asrc0 + (size_t)i * 32 * FFN + k0, 16);
#pragma unroll
            for (int i = 0; i < 8; i++)
                cpa16(bb + dsto0 + i * 4096, bsrc0 + (size_t)i * 32 * FFN + k0, 16);
        }
        cpa_commit();
        compute_tile(pre, sb + s * STAGE_BYTES, c);
    }

    // epilogue: scale + plain store to per-slot buffer
    int lane = tid & 31, warp = (tid >> 5) & 7;
    int wm = (warp & 1) * 64, wn = (warp >> 1) * 64;
    int g = lane >> 2, tg = lane & 3;
#pragma unroll
    for (int mt = 0; mt < 4; mt++) {
        int ml0 = wm + mt * 16 + g;
        int ml1 = ml0 + 8;
        float w0 = swv[ml0], w1v = swv[ml1];
        float* o0 = g_ho + (size_t)(m0 + ml0) * DIM + n0 + wn;
        float* o1 = g_ho + (size_t)(m0 + ml1) * DIM + n0 + wn;
#pragma unroll
        for (int nt = 0; nt < 8; nt++) {
            int nb = nt * 8 + tg * 2;
            *(float2*)(o0 + nb) = make_float2(c[mt][nt][0] * w0,  c[mt][nt][1] * w0);
            *(float2*)(o1 + nb) = make_float2(c[mt][nt][2] * w1v, c[mt][nt][3] * w1v);
        }
    }
}

// ---------------- launcher ----------------
extern "C" void kernel_launch(void* const* d_in, const int* in_sizes, int n_in,
                              void* d_out, int out_size) {
    const float* x  = (const float*)d_in[0];
    const float* rw = (const float*)d_in[1];
    const float* w1 = (const float*)d_in[2];
    const float* w2 = (const float*)d_in[3];
    float* out = (float*)d_out;

    static int configured = 0;
    if (!configured) {
        cudaFuncSetAttribute(gemm1_p, cudaFuncAttributeMaxDynamicSharedMemorySize, SMEM_TOTAL);
        cudaFuncSetAttribute(gemm2_p, cudaFuncAttributeMaxDynamicSharedMemorySize, SMEM_TOTAL);
        configured = 1;
    }

    const int n8tot = (NUM_TOK * DIM + NEXP * FFN * DIM + NEXP * DIM * FFN) / 8;

    prep_kernel<<<(n8tot + 255) / 256, 256>>>((const float4*)x, (const float4*)w1, (const float4*)w2);
    router_kernel<<<NUM_TOK / 8, 256>>>(x, rw);
    place_kernel<<<32, 256>>>();
    gemm1_p<<<dim3(MAX_MTILES, FFN / BN), 256, SMEM_TOTAL>>>();
    gemm2_p<<<dim3(MAX_MTILES, DIM / BN), 256, SMEM_TOTAL>>>();
    combine_kernel<<<(NUM_TOK * DIM / 4 + 255) / 256, 256>>>((float4*)out);
}

// round 12
// speedup vs baseline: 1.1424x; 1.1424x over previous
#include <cuda_runtime.h>
#include <cuda_fp16.h>
#include <cstdint>
#include <math.h>

// Problem constants
#define NUM_TOK 8192
#define DIM     1024
#define NEXP    8
#define FFN     4096

// GEMM tiling (fp16): 128x128 tiles, K-tile = 64 halves = 128 B/row
#define BM 128
#define BN 128
#define BKF 64
#define NSTAGE 3
#define MAX_SLOTS (2*NUM_TOK + NEXP*BM)     // 17408
#define MAX_MTILES (MAX_SLOTS/BM)           // 136

#define TILE_BYTES 16384                    // 128 rows x 128 B
#define STAGE_BYTES (2*TILE_BYTES)
#define SMEM_TOTAL (NSTAGE*STAGE_BYTES + 128)

// ---------------- device scratch ----------------
__device__ int    g_counts[NEXP];
__device__ int    g_fill[NEXP];
__device__ int    g_off[NEXP+1];
__device__ int    g_flag;
__device__ int    g_tok_e[2*NUM_TOK];
__device__ float  g_tok_w[2*NUM_TOK];
__device__ int    g_tok_slot[2*NUM_TOK];
__device__ int    g_slot_tok[MAX_SLOTS];
__device__ float  g_slot_w[MAX_SLOTS];
__device__ __half g_xh[(size_t)NUM_TOK * DIM];
__device__ __half g_w1h[(size_t)NEXP * FFN * DIM];
__device__ __half g_w2h[(size_t)NEXP * DIM * FFN];
__device__ __half g_hh[(size_t)MAX_SLOTS * FFN];
__device__ float  g_ho[(size_t)MAX_SLOTS * DIM];

// ---------------- helpers ----------------
__device__ __forceinline__ float gelu_exact(float v) {
    return 0.5f * v * (1.0f + erff(v * 0.70710678118654752f));
}
__device__ __forceinline__ uint32_t smem_u32(const void* p) {
    uint32_t a;
    asm("{ .reg .u64 t; cvta.to.shared.u64 t, %1; cvt.u32.u64 %0, t; }" : "=r"(a) : "l"(p));
    return a;
}
__device__ __forceinline__ void mma_f16(float c[4], const uint32_t a[4], const uint32_t b[2]) {
    asm volatile(
        "mma.sync.aligned.m16n8k16.row.col.f32.f16.f16.f32 "
        "{%0,%1,%2,%3},{%4,%5,%6,%7},{%8,%9},{%0,%1,%2,%3};"
        : "+f"(c[0]), "+f"(c[1]), "+f"(c[2]), "+f"(c[3])
        : "r"(a[0]), "r"(a[1]), "r"(a[2]), "r"(a[3]), "r"(b[0]), "r"(b[1]));
}
__device__ __forceinline__ void ldsm4(uint32_t& r0, uint32_t& r1, uint32_t& r2, uint32_t& r3,
                                      uint32_t addr) {
    asm volatile("ldmatrix.sync.aligned.m8n8.x4.shared.b16 {%0,%1,%2,%3}, [%4];"
                 : "=r"(r0), "=r"(r1), "=r"(r2), "=r"(r3) : "r"(addr));
}
__device__ __forceinline__ void cpa16(uint32_t dst, const void* src, int srcbytes) {
    asm volatile("cp.async.cg.shared.global [%0], [%1], 16, %2;"
                 :: "r"(dst), "l"(src), "r"(srcbytes) : "memory");
}
__device__ __forceinline__ void cpa_commit() { asm volatile("cp.async.commit_group;" ::: "memory"); }
__device__ __forceinline__ void cpa_wait1()  { asm volatile("cp.async.wait_group 1;" ::: "memory"); }

// ---------------- conversions ----------------
__device__ __forceinline__ void conv8(const float4* src, __half* dst, int j) {
    float4 v0 = src[2 * j], v1 = src[2 * j + 1];
    __half2 h0 = __floats2half2_rn(v0.x, v0.y);
    __half2 h1 = __floats2half2_rn(v0.z, v0.w);
    __half2 h2 = __floats2half2_rn(v1.x, v1.y);
    __half2 h3 = __floats2half2_rn(v1.z, v1.w);
    uint4 o;
    o.x = *(uint32_t*)&h0; o.y = *(uint32_t*)&h1;
    o.z = *(uint32_t*)&h2; o.w = *(uint32_t*)&h3;
    ((uint4*)dst)[j] = o;
}

// x + w1 -> fp16 (needed before gemm1)
__global__ void prep_xw1_kernel(const float4* __restrict__ x, const float4* __restrict__ w1) {
    const int n8x = NUM_TOK * DIM / 8;
    int i = blockIdx.x * blockDim.x + threadIdx.x;
    if (i < n8x) conv8(x, g_xh, i);
    else conv8(w1, g_w1h, i - n8x);
}

// w2 -> fp16 (needed before gemm2 only; overlapped with gemm1)
__global__ void prep_w2_kernel(const float4* __restrict__ w2) {
    int i = blockIdx.x * blockDim.x + threadIdx.x;
    if (i < NEXP * DIM * FFN / 8) conv8(w2, g_w2h, i);
}

// counters reset (head of routing stream)
__global__ void init_small_kernel() {
    int i = threadIdx.x;
    if (i < NEXP) { g_counts[i] = 0; g_fill[i] = 0; }
    if (i == NEXP) g_flag = 0;
}

// ---------------- router ----------------
__global__ void router_kernel(const float* __restrict__ x, const float* __restrict__ rw) {
    int warp = threadIdx.x >> 5, lane = threadIdx.x & 31;
    int t = blockIdx.x * 8 + warp;
    float acc[NEXP];
#pragma unroll
    for (int e = 0; e < NEXP; e++) acc[e] = 0.0f;
    const float* xp = x + (size_t)t * DIM;
    for (int k = lane; k < DIM; k += 32) {
        float xv = xp[k];
#pragma unroll
        for (int e = 0; e < NEXP; e++) acc[e] += xv * rw[e * DIM + k];
    }
#pragma unroll
    for (int e = 0; e < NEXP; e++) {
#pragma unroll
        for (int o = 16; o > 0; o >>= 1) acc[e] += __shfl_xor_sync(0xffffffffu, acc[e], o);
    }
    if (lane == 0) {
        int be = 0; float bv = acc[0];
#pragma unroll
        for (int e = 1; e < NEXP; e++) if (acc[e] > bv) { bv = acc[e]; be = e; }
        int be2 = -1; float bv2 = -1e30f;
#pragma unroll
        for (int e = 0; e < NEXP; e++) if (e != be && acc[e] > bv2) { bv2 = acc[e]; be2 = e; }
        float p0 = 1.0f / (1.0f + expf(bv2 - bv));
        g_tok_e[2 * t] = be;  g_tok_e[2 * t + 1] = be2;
        g_tok_w[2 * t] = p0;  g_tok_w[2 * t + 1] = 1.0f - p0;
        atomicAdd(&g_counts[be], 1);
        atomicAdd(&g_counts[be2], 1);
    }
}

// ---------------- place (offsets fused via device-flag spin; 32 resident blocks) ----------------
__global__ void place_kernel() {
    int flat = blockIdx.x * blockDim.x + threadIdx.x;
    if (flat == 0) {
        int o = 0;
        for (int e = 0; e < NEXP; e++) {
            g_off[e] = o;
            o += ((g_counts[e] + BM - 1) / BM) * BM;
        }
        g_off[NEXP] = o;
        __threadfence();
        atomicExch(&g_flag, 1);
    }
    while (atomicAdd(&g_flag, 0) == 0) {}
    __threadfence();

    if (flat < NEXP * BM) {
        int e = flat / BM, j = flat % BM;
        int idx = g_off[e] + g_counts[e] + j;
        if (idx < g_off[e + 1]) { g_slot_tok[idx] = -1; g_slot_w[idx] = 0.0f; }
    }
    int t = flat;
    if (t < NUM_TOK) {
#pragma unroll
        for (int k = 0; k < 2; k++) {
            int e = g_tok_e[2 * t + k];
            int p = atomicAdd(&g_fill[e], 1);
            int idx = g_off[e] + p;
            g_slot_tok[idx] = t;
            g_slot_w[idx] = g_tok_w[2 * t + k];
            g_tok_slot[2 * t + k] = idx;
        }
    }
}

// ---------------- combine: out[t] = ho[slot0(t)] + ho[slot1(t)] ----------------
__global__ void combine_kernel(float4* __restrict__ out) {
    const int D4 = DIM / 4;
    int i = blockIdx.x * blockDim.x + threadIdx.x;
    if (i >= NUM_TOK * D4) return;
    int t = i / D4, d = i % D4;
    const float4* h0 = (const float4*)(g_ho + (size_t)g_tok_slot[2 * t] * DIM);
    const float4* h1 = (const float4*)(g_ho + (size_t)g_tok_slot[2 * t + 1] * DIM);
    float4 a = h0[d], b = h1[d];
    out[i] = make_float4(a.x + b.x, a.y + b.y, a.z + b.z, a.w + b.w);
}

// ================= fp16 pipelined GEMM core (R10 config: 64x32 warp tiles) =================
struct Pre {
    uint32_t rowA[4];
    uint32_t rowB[2];
    uint32_t offA[4];
    uint32_t offB[4];
};

__device__ __forceinline__ void pre_init(Pre& p, int tid) {
    int warp = tid >> 5, lane = tid & 31;
    int wm = (warp >> 2) * 64, wn = (warp & 3) * 32;
    int rlA = lane & 15, selA = lane >> 4, rlA7 = rlA & 7;
    int nlB = ((lane >> 4) << 3) + (lane & 7);
    int selB = (lane >> 3) & 1, nlB7 = nlB & 7;
#pragma unroll
    for (int mt = 0; mt < 4; mt++) p.rowA[mt] = (uint32_t)(wm + mt * 16 + rlA) * 128;
#pragma unroll
    for (int q = 0; q < 2; q++)   p.rowB[q] = TILE_BYTES + (uint32_t)(wn + q * 16 + nlB) * 128;
#pragma unroll
    for (int ks = 0; ks < 4; ks++) {
        p.offA[ks] = ((uint32_t)((ks * 2 + selA) ^ rlA7)) << 4;
        p.offB[ks] = ((uint32_t)((ks * 2 + selB) ^ nlB7)) << 4;
    }
}

__device__ __forceinline__ void compute_tile(const Pre& p, uint32_t base, float c[4][4][4]) {
    uint32_t aR0 = base + p.rowA[0], aR1 = base + p.rowA[1];
    uint32_t aR2 = base + p.rowA[2], aR3 = base + p.rowA[3];
    uint32_t bR0 = base + p.rowB[0], bR1 = base + p.rowB[1];

    uint32_t b[2][4][2];
    ldsm4(b[0][0][0], b[0][0][1], b[0][1][0], b[0][1][1], bR0 + p.offB[0]);
    ldsm4(b[0][2][0], b[0][2][1], b[0][3][0], b[0][3][1], bR1 + p.offB[0]);

#pragma unroll
    for (int ks = 0; ks < 4; ks++) {
        const int cur = ks & 1, nxt = cur ^ 1;
        uint32_t a01[2][4];
        ldsm4(a01[0][0], a01[0][1], a01[0][2], a01[0][3], aR0 + p.offA[ks]);
        ldsm4(a01[1][0], a01[1][1], a01[1][2], a01[1][3], aR1 + p.offA[ks]);
        if (ks < 3) {
            ldsm4(b[nxt][0][0], b[nxt][0][1], b[nxt][1][0], b[nxt][1][1], bR0 + p.offB[ks + 1]);
            ldsm4(b[nxt][2][0], b[nxt][2][1], b[nxt][3][0], b[nxt][3][1], bR1 + p.offB[ks + 1]);
        }
#pragma unroll
        for (int mt = 0; mt < 2; mt++)
#pragma unroll
            for (int nt = 0; nt < 4; nt++)
                mma_f16(c[mt][nt], a01[mt], b[cur][nt]);

        uint32_t a23[2][4];
        ldsm4(a23[0][0], a23[0][1], a23[0][2], a23[0][3], aR2 + p.offA[ks]);
        ldsm4(a23[1][0], a23[1][1], a23[1][2], a23[1][3], aR3 + p.offA[ks]);
#pragma unroll
        for (int mt = 0; mt < 2; mt++)
#pragma unroll
            for (int nt = 0; nt < 4; nt++)
                mma_f16(c[mt + 2][nt], a23[mt], b[cur][nt]);
    }
}

// ---------------- GEMM1: h = gelu(x_gather @ W1^T) ----------------
__global__ void __launch_bounds__(256, 2)
gemm1_p() {
    extern __shared__ char smem[];
    __shared__ int stok[BM];

    const int tid = threadIdx.x;
    const int m0 = blockIdx.x * BM;
    if (m0 >= g_off[NEXP]) return;
    int e = 0;
    while (m0 >= g_off[e + 1]) e++;
    const __half* w1e = g_w1h + (size_t)e * FFN * DIM;
    const int n0 = blockIdx.y * BN;

    if (tid < BM) stok[tid] = g_slot_tok[m0 + tid];
    __syncthreads();

    uint32_t sb = (smem_u32(smem) + 127u) & ~127u;

    const __half* asrc[4]; const __half* bsrc[4];
    uint32_t dsto[4]; int asz[4];
#pragma unroll
    for (int i = 0; i < 4; i++) {
        int idx = tid + i * 256;
        int row = idx >> 3, ch = idx & 7;
        int tok = stok[row];
        asz[i]  = (tok < 0) ? 0 : 16;
        asrc[i] = g_xh + (size_t)((tok < 0) ? 0 : tok) * DIM + ch * 8;
        bsrc[i] = w1e + (size_t)(n0 + row) * DIM + ch * 8;
        dsto[i] = (uint32_t)row * 128 + ((uint32_t)(ch ^ (row & 7)) << 4);
    }

    Pre pre; pre_init(pre, tid);

    float c[4][4][4];
#pragma unroll
    for (int i = 0; i < 4; i++)
#pragma unroll
        for (int j = 0; j < 4; j++)
#pragma unroll
            for (int k = 0; k < 4; k++) c[i][j][k] = 0.0f;

    const int NK = DIM / BKF;   // 16
#pragma unroll
    for (int s = 0; s < 2; s++) {
        uint32_t ab = sb + s * STAGE_BYTES, bb = ab + TILE_BYTES;
#pragma unroll
        for (int i = 0; i < 4; i++) {
            cpa16(ab + dsto[i], asrc[i], asz[i]);
            cpa16(bb + dsto[i], bsrc[i], 16);
            asrc[i] += BKF; bsrc[i] += BKF;
        }
        cpa_commit();
    }

    for (int kt = 0; kt < NK; kt++) {
        int s = kt % NSTAGE;
        cpa_wait1();
        __syncthreads();
        if (kt + 2 < NK) {
            int sn = (kt + 2) % NSTAGE;
            uint32_t ab = sb + sn * STAGE_BYTES, bb = ab + TILE_BYTES;
#pragma unroll
            for (int i = 0; i < 4; i++) {
                cpa16(ab + dsto[i], asrc[i], asz[i]);
                cpa16(bb + dsto[i], bsrc[i], 16);
                asrc[i] += BKF; bsrc[i] += BKF;
            }
        }
        cpa_commit();
        compute_tile(pre, sb + s * STAGE_BYTES, c);
    }

    // epilogue: gelu -> fp16 h
    int lane = tid & 31, warp = tid >> 5;
    int wm = (warp >> 2) * 64, wn = (warp & 3) * 32;
    int g = lane >> 2, tg = lane & 3;
#pragma unroll
    for (int mt = 0; mt < 4; mt++) {
#pragma unroll
        for (int nt = 0; nt < 4; nt++) {
            int mb = m0 + wm + mt * 16 + g;
            int nb = n0 + wn + nt * 8 + tg * 2;
            __half2 v0 = __floats2half2_rn(gelu_exact(c[mt][nt][0]), gelu_exact(c[mt][nt][1]));
            __half2 v1 = __floats2half2_rn(gelu_exact(c[mt][nt][2]), gelu_exact(c[mt][nt][3]));
            *(__half2*)(g_hh + (size_t)mb * FFN + nb) = v0;
            *(__half2*)(g_hh + (size_t)(mb + 8) * FFN + nb) = v1;
        }
    }
}

// ---------------- GEMM2: ho[slot] = w_slot * (h[slot] @ W2^T), non-atomic ----------------
__global__ void __launch_bounds__(256, 2)
gemm2_p() {
    extern __shared__ char smem[];
    __shared__ float swv[BM];

    const int tid = threadIdx.x;
    const int m0 = blockIdx.x * BM;
    if (m0 >= g_off[NEXP]) return;
    int e = 0;
    while (m0 >= g_off[e + 1]) e++;
    const __half* w2e = g_w2h + (size_t)e * DIM * FFN;
    const int n0 = blockIdx.y * BN;

    if (tid < BM) swv[tid] = g_slot_w[m0 + tid];
    __syncthreads();

    uint32_t sb = (smem_u32(smem) + 127u) & ~127u;

    const __half* asrc[4]; const __half* bsrc[4];
    uint32_t dsto[4];
#pragma unroll
    for (int i = 0; i < 4; i++) {
        int idx = tid + i * 256;
        int row = idx >> 3, ch = idx & 7;
        asrc[i] = g_hh + (size_t)(m0 + row) * FFN + ch * 8;
        bsrc[i] = w2e + (size_t)(n0 + row) * FFN + ch * 8;
        dsto[i] = (uint32_t)row * 128 + ((uint32_t)(ch ^ (row & 7)) << 4);
    }

    Pre pre; pre_init(pre, tid);

    float c[4][4][4];
#pragma unroll
    for (int i = 0; i < 4; i++)
#pragma unroll
        for (int j = 0; j < 4; j++)
#pragma unroll
            for (int k = 0; k < 4; k++) c[i][j][k] = 0.0f;

    const int NK = FFN / BKF;   // 64
#pragma unroll
    for (int s = 0; s < 2; s++) {
        uint32_t ab = sb + s * STAGE_BYTES, bb = ab + TILE_BYTES;
#pragma unroll
        for (int i = 0; i < 4; i++) {
            cpa16(ab + dsto[i], asrc[i], 16);
            cpa16(bb + dsto[i], bsrc[i], 16);
            asrc[i] += BKF; bsrc[i] += BKF;
        }
        cpa_commit();
    }

    for (int kt = 0; kt < NK; kt++) {
        int s = kt % NSTAGE;
        cpa_wait1();
        __syncthreads();
        if (kt + 2 < NK) {
            int sn = (kt + 2) % NSTAGE;
            uint32_t ab = sb + sn * STAGE_BYTES, bb = ab + TILE_BYTES;
#pragma unroll
            for (int i = 0; i < 4; i++) {
                cpa16(ab + dsto[i], asrc[i], 16);
                cpa16(bb + dsto[i], bsrc[i], 16);
                asrc[i] += BKF; bsrc[i] += BKF;
            }
        }
        cpa_commit();
        compute_tile(pre, sb + s * STAGE_BYTES, c);
    }

    // epilogue: scale + plain store to per-slot buffer
    int lane = tid & 31, warp = tid >> 5;
    int wm = (warp >> 2) * 64, wn = (warp & 3) * 32;
    int g = lane >> 2, tg = lane & 3;
#pragma unroll
    for (int mt = 0; mt < 4; mt++) {
        int ml0 = wm + mt * 16 + g;
        int ml1 = ml0 + 8;
        float w0 = swv[ml0], w1v = swv[ml1];
        float* o0 = g_ho + (size_t)(m0 + ml0) * DIM + n0 + wn;
        float* o1 = g_ho + (size_t)(m0 + ml1) * DIM + n0 + wn;
#pragma unroll
        for (int nt = 0; nt < 4; nt++) {
            int nb = nt * 8 + tg * 2;
            *(float2*)(o0 + nb) = make_float2(c[mt][nt][0] * w0,  c[mt][nt][1] * w0);
            *(float2*)(o1 + nb) = make_float2(c[mt][nt][2] * w1v, c[mt][nt][3] * w1v);
        }
    }
}

// ---------------- launcher: multi-stream fork/join inside graph capture ----------------
extern "C" void kernel_launch(void* const* d_in, const int* in_sizes, int n_in,
                              void* d_out, int out_size) {
    const float* x  = (const float*)d_in[0];
    const float* rw = (const float*)d_in[1];
    const float* w1 = (const float*)d_in[2];
    const float* w2 = (const float*)d_in[3];
    float* out = (float*)d_out;

    static int configured = 0;
    static cudaStream_t s1, s2;
    static cudaEvent_t evRoot, evRoute, evW2;
    if (!configured) {
        cudaFuncSetAttribute(gemm1_p, cudaFuncAttributeMaxDynamicSharedMemorySize, SMEM_TOTAL);
        cudaFuncSetAttribute(gemm2_p, cudaFuncAttributeMaxDynamicSharedMemorySize, SMEM_TOTAL);
        cudaStreamCreateWithFlags(&s1, cudaStreamNonBlocking);
        cudaStreamCreateWithFlags(&s2, cudaStreamNonBlocking);
        cudaEventCreateWithFlags(&evRoot, cudaEventDisableTiming);
        cudaEventCreateWithFlags(&evRoute, cudaEventDisableTiming);
        cudaEventCreateWithFlags(&evW2, cudaEventDisableTiming);
        configured = 1;
    }

    const int n8x   = NUM_TOK * DIM / 8;
    const int n8w1  = NEXP * FFN * DIM / 8;
    const int n8w2  = NEXP * DIM * FFN / 8;
    const int n8xw1 = n8x + n8w1;

    // fork s1 (routing) and s2 (w2 conversion) off the captured main stream
    cudaEventRecord(evRoot, 0);
    cudaStreamWaitEvent(s1, evRoot, 0);
    cudaStreamWaitEvent(s2, evRoot, 0);

    // main stream: x + w1 -> fp16 (gemm1 prerequisites)
    prep_xw1_kernel<<<(n8xw1 + 255) / 256, 256>>>((const float4*)x, (const float4*)w1);

    // s1: counters -> router -> place
    init_small_kernel<<<1, 32, 0, s1>>>();
    router_kernel<<<NUM_TOK / 8, 256, 0, s1>>>(x, rw);
    place_kernel<<<32, 256, 0, s1>>>();
    cudaEventRecord(evRoute, s1);

    // s2: w2 -> fp16 (gemm2 prerequisite; overlaps gemm1)
    prep_w2_kernel<<<(n8w2 + 255) / 256, 256, 0, s2>>>((const float4*)w2);
    cudaEventRecord(evW2, s2);

    // join routing, run gemm1
    cudaStreamWaitEvent(0, evRoute, 0);
    gemm1_p<<<dim3(MAX_MTILES, FFN / BN), 256, SMEM_TOTAL>>>();

    // join w2 conversion, run gemm2 + combine
    cudaStreamWaitEvent(0, evW2, 0);
    gemm2_p<<<dim3(MAX_MTILES, DIM / BN), 256, SMEM_TOTAL>>>();
    combine_kernel<<<(NUM_TOK * DIM / 4 + 255) / 256, 256>>>((float4*)out);
}

// round 13
// speedup vs baseline: 1.1660x; 1.0207x over previous
#include <cuda_runtime.h>
#include <cuda_fp16.h>
#include <cstdint>
#include <math.h>

// Problem constants
#define NUM_TOK 8192
#define DIM     1024
#define NEXP    8
#define FFN     4096

// GEMM tiling (fp16): 128x128 tiles, K-tile = 64 halves = 128 B/row
#define BM 128
#define BN 128
#define BKF 64
#define NSTAGE 3
#define MAX_SLOTS (2*NUM_TOK + NEXP*BM)     // 17408
#define MAX_MTILES (MAX_SLOTS/BM)           // 136

#define TILE_BYTES 16384                    // 128 rows x 128 B
#define STAGE_BYTES (2*TILE_BYTES)
#define SMEM_TOTAL (NSTAGE*STAGE_BYTES + 128)

// ---------------- device scratch ----------------
__device__ int    g_counts[NEXP];
__device__ int    g_fill[NEXP];
__device__ int    g_off[NEXP+1];
__device__ int    g_tok_e[2*NUM_TOK];
__device__ float  g_tok_w[2*NUM_TOK];
__device__ int    g_tok_slot[2*NUM_TOK];
__device__ int    g_slot_tok[MAX_SLOTS];
__device__ float  g_slot_w[MAX_SLOTS];
__device__ __half g_xh[(size_t)NUM_TOK * DIM];
__device__ __half g_w1h[(size_t)NEXP * FFN * DIM];
__device__ __half g_w2h[(size_t)NEXP * DIM * FFN];
__device__ __half g_hh[(size_t)MAX_SLOTS * FFN];
__device__ float  g_ho[(size_t)MAX_SLOTS * DIM];

// ---------------- helpers ----------------
__device__ __forceinline__ float gelu_exact(float v) {
    return 0.5f * v * (1.0f + erff(v * 0.70710678118654752f));
}
__device__ __forceinline__ uint32_t smem_u32(const void* p) {
    uint32_t a;
    asm("{ .reg .u64 t; cvta.to.shared.u64 t, %1; cvt.u32.u64 %0, t; }" : "=r"(a) : "l"(p));
    return a;
}
__device__ __forceinline__ void mma_f16(float c[4], const uint32_t a[4], const uint32_t b[2]) {
    asm volatile(
        "mma.sync.aligned.m16n8k16.row.col.f32.f16.f16.f32 "
        "{%0,%1,%2,%3},{%4,%5,%6,%7},{%8,%9},{%0,%1,%2,%3};"
        : "+f"(c[0]), "+f"(c[1]), "+f"(c[2]), "+f"(c[3])
        : "r"(a[0]), "r"(a[1]), "r"(a[2]), "r"(a[3]), "r"(b[0]), "r"(b[1]));
}
__device__ __forceinline__ void ldsm4(uint32_t& r0, uint32_t& r1, uint32_t& r2, uint32_t& r3,
                                      uint32_t addr) {
    asm volatile("ldmatrix.sync.aligned.m8n8.x4.shared.b16 {%0,%1,%2,%3}, [%4];"
                 : "=r"(r0), "=r"(r1), "=r"(r2), "=r"(r3) : "r"(addr));
}
__device__ __forceinline__ void cpa16(uint32_t dst, const void* src, int srcbytes) {
    asm volatile("cp.async.cg.shared.global [%0], [%1], 16, %2;"
                 :: "r"(dst), "l"(src), "r"(srcbytes) : "memory");
}
__device__ __forceinline__ void cpa_commit() { asm volatile("cp.async.commit_group;" ::: "memory"); }
__device__ __forceinline__ void cpa_wait1()  { asm volatile("cp.async.wait_group 1;" ::: "memory"); }

// ---------------- conversions ----------------
__device__ __forceinline__ void conv8(const float4* src, __half* dst, int j) {
    float4 v0 = src[2 * j], v1 = src[2 * j + 1];
    __half2 h0 = __floats2half2_rn(v0.x, v0.y);
    __half2 h1 = __floats2half2_rn(v0.z, v0.w);
    __half2 h2 = __floats2half2_rn(v1.x, v1.y);
    __half2 h3 = __floats2half2_rn(v1.z, v1.w);
    uint4 o;
    o.x = *(uint32_t*)&h0; o.y = *(uint32_t*)&h1;
    o.z = *(uint32_t*)&h2; o.w = *(uint32_t*)&h3;
    ((uint4*)dst)[j] = o;
}

__global__ void prep_xw1_kernel(const float4* __restrict__ x, const float4* __restrict__ w1) {
    const int n8x = NUM_TOK * DIM / 8;
    int i = blockIdx.x * blockDim.x + threadIdx.x;
    if (i < n8x) conv8(x, g_xh, i);
    else conv8(w1, g_w1h, i - n8x);
}

__global__ void prep_w2_kernel(const float4* __restrict__ w2) {
    int i = blockIdx.x * blockDim.x + threadIdx.x;
    if (i < NEXP * DIM * FFN / 8) conv8(w2, g_w2h, i);
}

__global__ void init_small_kernel() {
    int i = threadIdx.x;
    if (i < NEXP) { g_counts[i] = 0; g_fill[i] = 0; }
}

// ---------------- router ----------------
__global__ void router_kernel(const float* __restrict__ x, const float* __restrict__ rw) {
    int warp = threadIdx.x >> 5, lane = threadIdx.x & 31;
    int t = blockIdx.x * 8 + warp;
    float acc[NEXP];
#pragma unroll
    for (int e = 0; e < NEXP; e++) acc[e] = 0.0f;
    const float* xp = x + (size_t)t * DIM;
    for (int k = lane; k < DIM; k += 32) {
        float xv = xp[k];
#pragma unroll
        for (int e = 0; e < NEXP; e++) acc[e] += xv * rw[e * DIM + k];
    }
#pragma unroll
    for (int e = 0; e < NEXP; e++) {
#pragma unroll
        for (int o = 16; o > 0; o >>= 1) acc[e] += __shfl_xor_sync(0xffffffffu, acc[e], o);
    }
    if (lane == 0) {
        int be = 0; float bv = acc[0];
#pragma unroll
        for (int e = 1; e < NEXP; e++) if (acc[e] > bv) { bv = acc[e]; be = e; }
        int be2 = -1; float bv2 = -1e30f;
#pragma unroll
        for (int e = 0; e < NEXP; e++) if (e != be && acc[e] > bv2) { bv2 = acc[e]; be2 = e; }
        float p0 = 1.0f / (1.0f + expf(bv2 - bv));
        g_tok_e[2 * t] = be;  g_tok_e[2 * t + 1] = be2;
        g_tok_w[2 * t] = p0;  g_tok_w[2 * t + 1] = 1.0f - p0;
        atomicAdd(&g_counts[be], 1);
        atomicAdd(&g_counts[be2], 1);
    }
}

// ---------------- offsets (1 block; no cross-block spin anywhere) ----------------
__global__ void offsets_kernel() {
    if (threadIdx.x == 0) {
        int o = 0;
        for (int e = 0; e < NEXP; e++) {
            g_off[e] = o;
            o += ((g_counts[e] + BM - 1) / BM) * BM;
        }
        g_off[NEXP] = o;
    }
}

// ---------------- place (offsets already computed) ----------------
__global__ void place_kernel() {
    int flat = blockIdx.x * blockDim.x + threadIdx.x;
    if (flat < NEXP * BM) {
        int e = flat / BM, j = flat % BM;
        int idx = g_off[e] + g_counts[e] + j;
        if (idx < g_off[e + 1]) { g_slot_tok[idx] = -1; g_slot_w[idx] = 0.0f; }
    }
    int t = flat;
    if (t < NUM_TOK) {
#pragma unroll
        for (int k = 0; k < 2; k++) {
            int e = g_tok_e[2 * t + k];
            int p = atomicAdd(&g_fill[e], 1);
            int idx = g_off[e] + p;
            g_slot_tok[idx] = t;
            g_slot_w[idx] = g_tok_w[2 * t + k];
            g_tok_slot[2 * t + k] = idx;
        }
    }
}

// ---------------- combine: out[t] = ho[slot0(t)] + ho[slot1(t)] ----------------
__global__ void combine_kernel(float4* __restrict__ out) {
    const int D4 = DIM / 4;
    int i = blockIdx.x * blockDim.x + threadIdx.x;
    if (i >= NUM_TOK * D4) return;
    int t = i / D4, d = i % D4;
    const float4* h0 = (const float4*)(g_ho + (size_t)g_tok_slot[2 * t] * DIM);
    const float4* h1 = (const float4*)(g_ho + (size_t)g_tok_slot[2 * t + 1] * DIM);
    float4 a = h0[d], b = h1[d];
    out[i] = make_float4(a.x + b.x, a.y + b.y, a.z + b.z, a.w + b.w);
}

// ================= fp16 pipelined GEMM core (64x32 warp tiles) =================
struct Pre {
    uint32_t rowA[4];
    uint32_t rowB[2];
    uint32_t offA[4];
    uint32_t offB[4];
};

__device__ __forceinline__ void pre_init(Pre& p, int tid) {
    int warp = tid >> 5, lane = tid & 31;
    int wm = (warp >> 2) * 64, wn = (warp & 3) * 32;
    int rlA = lane & 15, selA = lane >> 4, rlA7 = rlA & 7;
    int nlB = ((lane >> 4) << 3) + (lane & 7);
    int selB = (lane >> 3) & 1, nlB7 = nlB & 7;
#pragma unroll
    for (int mt = 0; mt < 4; mt++) p.rowA[mt] = (uint32_t)(wm + mt * 16 + rlA) * 128;
#pragma unroll
    for (int q = 0; q < 2; q++)   p.rowB[q] = TILE_BYTES + (uint32_t)(wn + q * 16 + nlB) * 128;
#pragma unroll
    for (int ks = 0; ks < 4; ks++) {
        p.offA[ks] = ((uint32_t)((ks * 2 + selA) ^ rlA7)) << 4;
        p.offB[ks] = ((uint32_t)((ks * 2 + selB) ^ nlB7)) << 4;
    }
}

__device__ __forceinline__ void compute_tile(const Pre& p, uint32_t base, float c[4][4][4]) {
    uint32_t aR0 = base + p.rowA[0], aR1 = base + p.rowA[1];
    uint32_t aR2 = base + p.rowA[2], aR3 = base + p.rowA[3];
    uint32_t bR0 = base + p.rowB[0], bR1 = base + p.rowB[1];

    uint32_t b[2][4][2];
    ldsm4(b[0][0][0], b[0][0][1], b[0][1][0], b[0][1][1], bR0 + p.offB[0]);
    ldsm4(b[0][2][0], b[0][2][1], b[0][3][0], b[0][3][1], bR1 + p.offB[0]);

#pragma unroll
    for (int ks = 0; ks < 4; ks++) {
        const int cur = ks & 1, nxt = cur ^ 1;
        uint32_t a01[2][4];
        ldsm4(a01[0][0], a01[0][1], a01[0][2], a01[0][3], aR0 + p.offA[ks]);
        ldsm4(a01[1][0], a01[1][1], a01[1][2], a01[1][3], aR1 + p.offA[ks]);
        if (ks < 3) {
            ldsm4(b[nxt][0][0], b[nxt][0][1], b[nxt][1][0], b[nxt][1][1], bR0 + p.offB[ks + 1]);
            ldsm4(b[nxt][2][0], b[nxt][2][1], b[nxt][3][0], b[nxt][3][1], bR1 + p.offB[ks + 1]);
        }
#pragma unroll
        for (int mt = 0; mt < 2; mt++)
#pragma unroll
            for (int nt = 0; nt < 4; nt++)
                mma_f16(c[mt][nt], a01[mt], b[cur][nt]);

        uint32_t a23[2][4];
        ldsm4(a23[0][0], a23[0][1], a23[0][2], a23[0][3], aR2 + p.offA[ks]);
        ldsm4(a23[1][0], a23[1][1], a23[1][2], a23[1][3], aR3 + p.offA[ks]);
#pragma unroll
        for (int mt = 0; mt < 2; mt++)
#pragma unroll
            for (int nt = 0; nt < 4; nt++)
                mma_f16(c[mt + 2][nt], a23[mt], b[cur][nt]);
    }
}

// ---------------- GEMM1: h = gelu(x_gather @ W1^T) ----------------
__global__ void __launch_bounds__(256, 2)
gemm1_p() {
    extern __shared__ char smem[];
    __shared__ int stok[BM];

    const int tid = threadIdx.x;
    const int m0 = blockIdx.x * BM;
    if (m0 >= g_off[NEXP]) return;
    int e = 0;
    while (m0 >= g_off[e + 1]) e++;
    const __half* w1e = g_w1h + (size_t)e * FFN * DIM;
    const int n0 = blockIdx.y * BN;

    if (tid < BM) stok[tid] = g_slot_tok[m0 + tid];
    __syncthreads();

    uint32_t sb = (smem_u32(smem) + 127u) & ~127u;

    const __half* asrc[4]; const __half* bsrc[4];
    uint32_t dsto[4]; int asz[4];
#pragma unroll
    for (int i = 0; i < 4; i++) {
        int idx = tid + i * 256;
        int row = idx >> 3, ch = idx & 7;
        int tok = stok[row];
        asz[i]  = (tok < 0) ? 0 : 16;
        asrc[i] = g_xh + (size_t)((tok < 0) ? 0 : tok) * DIM + ch * 8;
        bsrc[i] = w1e + (size_t)(n0 + row) * DIM + ch * 8;
        dsto[i] = (uint32_t)row * 128 + ((uint32_t)(ch ^ (row & 7)) << 4);
    }

    Pre pre; pre_init(pre, tid);

    float c[4][4][4];
#pragma unroll
    for (int i = 0; i < 4; i++)
#pragma unroll
        for (int j = 0; j < 4; j++)
#pragma unroll
            for (int k = 0; k < 4; k++) c[i][j][k] = 0.0f;

    const int NK = DIM / BKF;   // 16
#pragma unroll
    for (int s = 0; s < 2; s++) {
        uint32_t ab = sb + s * STAGE_BYTES, bb = ab + TILE_BYTES;
#pragma unroll
        for (int i = 0; i < 4; i++) {
            cpa16(ab + dsto[i], asrc[i], asz[i]);
            cpa16(bb + dsto[i], bsrc[i], 16);
            asrc[i] += BKF; bsrc[i] += BKF;
        }
        cpa_commit();
    }

    for (int kt = 0; kt < NK; kt++) {
        int s = kt % NSTAGE;
        cpa_wait1();
        __syncthreads();
        if (kt + 2 < NK) {
            int sn = (kt + 2) % NSTAGE;
            uint32_t ab = sb + sn * STAGE_BYTES, bb = ab + TILE_BYTES;
#pragma unroll
            for (int i = 0; i < 4; i++) {
                cpa16(ab + dsto[i], asrc[i], asz[i]);
                cpa16(bb + dsto[i], bsrc[i], 16);
                asrc[i] += BKF; bsrc[i] += BKF;
            }
        }
        cpa_commit();
        compute_tile(pre, sb + s * STAGE_BYTES, c);
    }

    // epilogue: gelu -> fp16 h
    int lane = tid & 31, warp = tid >> 5;
    int wm = (warp >> 2) * 64, wn = (warp & 3) * 32;
    int g = lane >> 2, tg = lane & 3;
#pragma unroll
    for (int mt = 0; mt < 4; mt++) {
#pragma unroll
        for (int nt = 0; nt < 4; nt++) {
            int mb = m0 + wm + mt * 16 + g;
            int nb = n0 + wn + nt * 8 + tg * 2;
            __half2 v0 = __floats2half2_rn(gelu_exact(c[mt][nt][0]), gelu_exact(c[mt][nt][1]));
            __half2 v1 = __floats2half2_rn(gelu_exact(c[mt][nt][2]), gelu_exact(c[mt][nt][3]));
            *(__half2*)(g_hh + (size_t)mb * FFN + nb) = v0;
            *(__half2*)(g_hh + (size_t)(mb + 8) * FFN + nb) = v1;
        }
    }
}

// ---------------- GEMM2: ho[slot] = w_slot * (h[slot] @ W2^T), non-atomic ----------------
__global__ void __launch_bounds__(256, 2)
gemm2_p() {
    extern __shared__ char smem[];
    __shared__ float swv[BM];

    const int tid = threadIdx.x;
    const int m0 = blockIdx.x * BM;
    if (m0 >= g_off[NEXP]) return;
    int e = 0;
    while (m0 >= g_off[e + 1]) e++;
    const __half* w2e = g_w2h + (size_t)e * DIM * FFN;
    const int n0 = blockIdx.y * BN;

    if (tid < BM) swv[tid] = g_slot_w[m0 + tid];
    __syncthreads();

    uint32_t sb = (smem_u32(smem) + 127u) & ~127u;

    const __half* asrc[4]; const __half* bsrc[4];
    uint32_t dsto[4];
#pragma unroll
    for (int i = 0; i < 4; i++) {
        int idx = tid + i * 256;
        int row = idx >> 3, ch = idx & 7;
        asrc[i] = g_hh + (size_t)(m0 + row) * FFN + ch * 8;
        bsrc[i] = w2e + (size_t)(n0 + row) * FFN + ch * 8;
        dsto[i] = (uint32_t)row * 128 + ((uint32_t)(ch ^ (row & 7)) << 4);
    }

    Pre pre; pre_init(pre, tid);

    float c[4][4][4];
#pragma unroll
    for (int i = 0; i < 4; i++)
#pragma unroll
        for (int j = 0; j < 4; j++)
#pragma unroll
            for (int k = 0; k < 4; k++) c[i][j][k] = 0.0f;

    const int NK = FFN / BKF;   // 64
#pragma unroll
    for (int s = 0; s < 2; s++) {
        uint32_t ab = sb + s * STAGE_BYTES, bb = ab + TILE_BYTES;
#pragma unroll
        for (int i = 0; i < 4; i++) {
            cpa16(ab + dsto[i], asrc[i], 16);
            cpa16(bb + dsto[i], bsrc[i], 16);
            asrc[i] += BKF; bsrc[i] += BKF;
        }
        cpa_commit();
    }

    for (int kt = 0; kt < NK; kt++) {
        int s = kt % NSTAGE;
        cpa_wait1();
        __syncthreads();
        if (kt + 2 < NK) {
            int sn = (kt + 2) % NSTAGE;
            uint32_t ab = sb + sn * STAGE_BYTES, bb = ab + TILE_BYTES;
#pragma unroll
            for (int i = 0; i < 4; i++) {
                cpa16(ab + dsto[i], asrc[i], 16);
                cpa16(bb + dsto[i], bsrc[i], 16);
                asrc[i] += BKF; bsrc[i] += BKF;
            }
        }
        cpa_commit();
        compute_tile(pre, sb + s * STAGE_BYTES, c);
    }

    // epilogue: scale + plain store to per-slot buffer
    int lane = tid & 31, warp = tid >> 5;
    int wm = (warp >> 2) * 64, wn = (warp & 3) * 32;
    int g = lane >> 2, tg = lane & 3;
#pragma unroll
    for (int mt = 0; mt < 4; mt++) {
        int ml0 = wm + mt * 16 + g;
        int ml1 = ml0 + 8;
        float w0 = swv[ml0], w1v = swv[ml1];
        float* o0 = g_ho + (size_t)(m0 + ml0) * DIM + n0 + wn;
        float* o1 = g_ho + (size_t)(m0 + ml1) * DIM + n0 + wn;
#pragma unroll
        for (int nt = 0; nt < 4; nt++) {
            int nb = nt * 8 + tg * 2;
            *(float2*)(o0 + nb) = make_float2(c[mt][nt][0] * w0,  c[mt][nt][1] * w0);
            *(float2*)(o1 + nb) = make_float2(c[mt][nt][2] * w1v, c[mt][nt][3] * w1v);
        }
    }
}

// ---------------- launcher: fork/join, no spin kernels ----------------
extern "C" void kernel_launch(void* const* d_in, const int* in_sizes, int n_in,
                              void* d_out, int out_size) {
    const float* x  = (const float*)d_in[0];
    const float* rw = (const float*)d_in[1];
    const float* w1 = (const float*)d_in[2];
    const float* w2 = (const float*)d_in[3];
    float* out = (float*)d_out;

    static int configured = 0;
    static cudaStream_t s1, s2;
    static cudaEvent_t evRoot, evRoute, evW2;
    if (!configured) {
        cudaFuncSetAttribute(gemm1_p, cudaFuncAttributeMaxDynamicSharedMemorySize, SMEM_TOTAL);
        cudaFuncSetAttribute(gemm2_p, cudaFuncAttributeMaxDynamicSharedMemorySize, SMEM_TOTAL);
        cudaStreamCreateWithFlags(&s1, cudaStreamNonBlocking);
        cudaStreamCreateWithFlags(&s2, cudaStreamNonBlocking);
        cudaEventCreateWithFlags(&evRoot, cudaEventDisableTiming);
        cudaEventCreateWithFlags(&evRoute, cudaEventDisableTiming);
        cudaEventCreateWithFlags(&evW2, cudaEventDisableTiming);
        configured = 1;
    }

    const int n8x   = NUM_TOK * DIM / 8;
    const int n8w1  = NEXP * FFN * DIM / 8;
    const int n8w2  = NEXP * DIM * FFN / 8;
    const int n8xw1 = n8x + n8w1;

    // fork s1 (routing chain) and s2 (w2 conversion) off the captured stream
    cudaEventRecord(evRoot, 0);
    cudaStreamWaitEvent(s1, evRoot, 0);
    cudaStreamWaitEvent(s2, evRoot, 0);

    // main stream: x + w1 -> fp16 (gemm1 prerequisite)
    prep_xw1_kernel<<<(n8xw1 + 255) / 256, 256>>>((const float4*)x, (const float4*)w1);

    // s1: counters -> router -> offsets -> place (all dependency-clean, no spins)
    init_small_kernel<<<1, 32, 0, s1>>>();
    router_kernel<<<NUM_TOK / 8, 256, 0, s1>>>(x, rw);
    offsets_kernel<<<1, 32, 0, s1>>>();
    place_kernel<<<32, 256, 0, s1>>>();
    cudaEventRecord(evRoute, s1);

    // s2: w2 -> fp16 (needed only by gemm2; overlaps gemm1)
    prep_w2_kernel<<<(n8w2 + 255) / 256, 256, 0, s2>>>((const float4*)w2);
    cudaEventRecord(evW2, s2);

    // join routing, run gemm1
    cudaStreamWaitEvent(0, evRoute, 0);
    gemm1_p<<<dim3(MAX_MTILES, FFN / BN), 256, SMEM_TOTAL>>>();

    // join w2 conversion, run gemm2 + combine
    cudaStreamWaitEvent(0, evW2, 0);
    gemm2_p<<<dim3(MAX_MTILES, DIM / BN), 256, SMEM_TOTAL>>>();
    combine_kernel<<<(NUM_TOK * DIM / 4 + 255) / 256, 256>>>((float4*)out);
}

// round 14
// speedup vs baseline: 1.1713x; 1.0045x over previous
#include <cuda_runtime.h>
#include <cuda_fp16.h>
#include <cstdint>
#include <math.h>

// Problem constants
#define NUM_TOK 8192
#define DIM     1024
#define NEXP    8
#define FFN     4096

// GEMM tiling (fp16): 128x128 tiles, K-tile = 64 halves = 128 B/row
#define BM 128
#define BN 128
#define BKF 64
#define NSTAGE 3
#define MAX_SLOTS (2*NUM_TOK + NEXP*BM)     // 17408
#define MAX_MTILES (MAX_SLOTS/BM)           // 136

#define TILE_BYTES 16384                    // 128 rows x 128 B
#define STAGE_BYTES (2*TILE_BYTES)
#define SMEM_TOTAL (NSTAGE*STAGE_BYTES + 128)

// ---------------- device scratch ----------------
__device__ int    g_counts[NEXP];
__device__ int    g_fill[NEXP];
__device__ int    g_off[NEXP+1];
__device__ int    g_tok_e[2*NUM_TOK];
__device__ float  g_tok_w[2*NUM_TOK];
__device__ int    g_slot_tok[MAX_SLOTS];
__device__ float  g_slot_w[MAX_SLOTS];
__device__ __half g_xh[(size_t)NUM_TOK * DIM];
__device__ __half g_w1h[(size_t)NEXP * FFN * DIM];
__device__ __half g_w2h[(size_t)NEXP * DIM * FFN];
__device__ __half g_hh[(size_t)MAX_SLOTS * FFN];

// ---------------- helpers ----------------
__device__ __forceinline__ float gelu_exact(float v) {
    return 0.5f * v * (1.0f + erff(v * 0.70710678118654752f));
}
__device__ __forceinline__ uint32_t smem_u32(const void* p) {
    uint32_t a;
    asm("{ .reg .u64 t; cvta.to.shared.u64 t, %1; cvt.u32.u64 %0, t; }" : "=r"(a) : "l"(p));
    return a;
}
__device__ __forceinline__ void mma_f16(float c[4], const uint32_t a[4], const uint32_t b[2]) {
    asm volatile(
        "mma.sync.aligned.m16n8k16.row.col.f32.f16.f16.f32 "
        "{%0,%1,%2,%3},{%4,%5,%6,%7},{%8,%9},{%0,%1,%2,%3};"
        : "+f"(c[0]), "+f"(c[1]), "+f"(c[2]), "+f"(c[3])
        : "r"(a[0]), "r"(a[1]), "r"(a[2]), "r"(a[3]), "r"(b[0]), "r"(b[1]));
}
__device__ __forceinline__ void ldsm4(uint32_t& r0, uint32_t& r1, uint32_t& r2, uint32_t& r3,
                                      uint32_t addr) {
    asm volatile("ldmatrix.sync.aligned.m8n8.x4.shared.b16 {%0,%1,%2,%3}, [%4];"
                 : "=r"(r0), "=r"(r1), "=r"(r2), "=r"(r3) : "r"(addr));
}
__device__ __forceinline__ void cpa16(uint32_t dst, const void* src, int srcbytes) {
    asm volatile("cp.async.cg.shared.global [%0], [%1], 16, %2;"
                 :: "r"(dst), "l"(src), "r"(srcbytes) : "memory");
}
__device__ __forceinline__ void cpa_commit() { asm volatile("cp.async.commit_group;" ::: "memory"); }
__device__ __forceinline__ void cpa_wait1()  { asm volatile("cp.async.wait_group 1;" ::: "memory"); }

// ---------------- conversions ----------------
__device__ __forceinline__ void conv8(const float4* src, __half* dst, int j) {
    float4 v0 = src[2 * j], v1 = src[2 * j + 1];
    __half2 h0 = __floats2half2_rn(v0.x, v0.y);
    __half2 h1 = __floats2half2_rn(v0.z, v0.w);
    __half2 h2 = __floats2half2_rn(v1.x, v1.y);
    __half2 h3 = __floats2half2_rn(v1.z, v1.w);
    uint4 o;
    o.x = *(uint32_t*)&h0; o.y = *(uint32_t*)&h1;
    o.z = *(uint32_t*)&h2; o.w = *(uint32_t*)&h3;
    ((uint4*)dst)[j] = o;
}

__global__ void prep_xw1_kernel(const float4* __restrict__ x, const float4* __restrict__ w1) {
    const int n8x = NUM_TOK * DIM / 8;
    int i = blockIdx.x * blockDim.x + threadIdx.x;
    if (i < n8x) conv8(x, g_xh, i);
    else conv8(w1, g_w1h, i - n8x);
}

__global__ void prep_w2_kernel(const float4* __restrict__ w2) {
    int i = blockIdx.x * blockDim.x + threadIdx.x;
    if (i < NEXP * DIM * FFN / 8) conv8(w2, g_w2h, i);
}

__global__ void zero_out_kernel(float4* __restrict__ out, int n4) {
    int i = blockIdx.x * blockDim.x + threadIdx.x;
    if (i < n4) out[i] = make_float4(0.f, 0.f, 0.f, 0.f);
}

__global__ void init_small_kernel() {
    int i = threadIdx.x;
    if (i < NEXP) { g_counts[i] = 0; g_fill[i] = 0; }
}

// ---------------- router ----------------
__global__ void router_kernel(const float* __restrict__ x, const float* __restrict__ rw) {
    int warp = threadIdx.x >> 5, lane = threadIdx.x & 31;
    int t = blockIdx.x * 8 + warp;
    float acc[NEXP];
#pragma unroll
    for (int e = 0; e < NEXP; e++) acc[e] = 0.0f;
    const float* xp = x + (size_t)t * DIM;
    for (int k = lane; k < DIM; k += 32) {
        float xv = xp[k];
#pragma unroll
        for (int e = 0; e < NEXP; e++) acc[e] += xv * rw[e * DIM + k];
    }
#pragma unroll
    for (int e = 0; e < NEXP; e++) {
#pragma unroll
        for (int o = 16; o > 0; o >>= 1) acc[e] += __shfl_xor_sync(0xffffffffu, acc[e], o);
    }
    if (lane == 0) {
        int be = 0; float bv = acc[0];
#pragma unroll
        for (int e = 1; e < NEXP; e++) if (acc[e] > bv) { bv = acc[e]; be = e; }
        int be2 = -1; float bv2 = -1e30f;
#pragma unroll
        for (int e = 0; e < NEXP; e++) if (e != be && acc[e] > bv2) { bv2 = acc[e]; be2 = e; }
        float p0 = 1.0f / (1.0f + expf(bv2 - bv));
        g_tok_e[2 * t] = be;  g_tok_e[2 * t + 1] = be2;
        g_tok_w[2 * t] = p0;  g_tok_w[2 * t + 1] = 1.0f - p0;
        atomicAdd(&g_counts[be], 1);
        atomicAdd(&g_counts[be2], 1);
    }
}

// ---------------- offsets (1 block) ----------------
__global__ void offsets_kernel() {
    if (threadIdx.x == 0) {
        int o = 0;
        for (int e = 0; e < NEXP; e++) {
            g_off[e] = o;
            o += ((g_counts[e] + BM - 1) / BM) * BM;
        }
        g_off[NEXP] = o;
    }
}

// ---------------- place ----------------
__global__ void place_kernel() {
    int flat = blockIdx.x * blockDim.x + threadIdx.x;
    if (flat < NEXP * BM) {
        int e = flat / BM, j = flat % BM;
        int idx = g_off[e] + g_counts[e] + j;
        if (idx < g_off[e + 1]) { g_slot_tok[idx] = -1; g_slot_w[idx] = 0.0f; }
    }
    int t = flat;
    if (t < NUM_TOK) {
#pragma unroll
        for (int k = 0; k < 2; k++) {
            int e = g_tok_e[2 * t + k];
            int p = atomicAdd(&g_fill[e], 1);
            int idx = g_off[e] + p;
            g_slot_tok[idx] = t;
            g_slot_w[idx] = g_tok_w[2 * t + k];
        }
    }
}

// ================= fp16 pipelined GEMM core (64x32 warp tiles) =================
struct Pre {
    uint32_t rowA[4];
    uint32_t rowB[2];
    uint32_t offA[4];
    uint32_t offB[4];
};

__device__ __forceinline__ void pre_init(Pre& p, int tid) {
    int warp = tid >> 5, lane = tid & 31;
    int wm = (warp >> 2) * 64, wn = (warp & 3) * 32;
    int rlA = lane & 15, selA = lane >> 4, rlA7 = rlA & 7;
    int nlB = ((lane >> 4) << 3) + (lane & 7);
    int selB = (lane >> 3) & 1, nlB7 = nlB & 7;
#pragma unroll
    for (int mt = 0; mt < 4; mt++) p.rowA[mt] = (uint32_t)(wm + mt * 16 + rlA) * 128;
#pragma unroll
    for (int q = 0; q < 2; q++)   p.rowB[q] = TILE_BYTES + (uint32_t)(wn + q * 16 + nlB) * 128;
#pragma unroll
    for (int ks = 0; ks < 4; ks++) {
        p.offA[ks] = ((uint32_t)((ks * 2 + selA) ^ rlA7)) << 4;
        p.offB[ks] = ((uint32_t)((ks * 2 + selB) ^ nlB7)) << 4;
    }
}

__device__ __forceinline__ void compute_tile(const Pre& p, uint32_t base, float c[4][4][4]) {
    uint32_t aR0 = base + p.rowA[0], aR1 = base + p.rowA[1];
    uint32_t aR2 = base + p.rowA[2], aR3 = base + p.rowA[3];
    uint32_t bR0 = base + p.rowB[0], bR1 = base + p.rowB[1];

    uint32_t b[2][4][2];
    ldsm4(b[0][0][0], b[0][0][1], b[0][1][0], b[0][1][1], bR0 + p.offB[0]);
    ldsm4(b[0][2][0], b[0][2][1], b[0][3][0], b[0][3][1], bR1 + p.offB[0]);

#pragma unroll
    for (int ks = 0; ks < 4; ks++) {
        const int cur = ks & 1, nxt = cur ^ 1;
        uint32_t a01[2][4];
        ldsm4(a01[0][0], a01[0][1], a01[0][2], a01[0][3], aR0 + p.offA[ks]);
        ldsm4(a01[1][0], a01[1][1], a01[1][2], a01[1][3], aR1 + p.offA[ks]);
        if (ks < 3) {
            ldsm4(b[nxt][0][0], b[nxt][0][1], b[nxt][1][0], b[nxt][1][1], bR0 + p.offB[ks + 1]);
            ldsm4(b[nxt][2][0], b[nxt][2][1], b[nxt][3][0], b[nxt][3][1], bR1 + p.offB[ks + 1]);
        }
#pragma unroll
        for (int mt = 0; mt < 2; mt++)
#pragma unroll
            for (int nt = 0; nt < 4; nt++)
                mma_f16(c[mt][nt], a01[mt], b[cur][nt]);

        uint32_t a23[2][4];
        ldsm4(a23[0][0], a23[0][1], a23[0][2], a23[0][3], aR2 + p.offA[ks]);
        ldsm4(a23[1][0], a23[1][1], a23[1][2], a23[1][3], aR3 + p.offA[ks]);
#pragma unroll
        for (int mt = 0; mt < 2; mt++)
#pragma unroll
            for (int nt = 0; nt < 4; nt++)
                mma_f16(c[mt + 2][nt], a23[mt], b[cur][nt]);
    }
}

// ---------------- GEMM1: h = gelu(x_gather @ W1^T) ----------------
__global__ void __launch_bounds__(256, 2)
gemm1_p() {
    extern __shared__ char smem[];
    __shared__ int stok[BM];

    const int tid = threadIdx.x;
    const int m0 = blockIdx.x * BM;
    if (m0 >= g_off[NEXP]) return;
    int e = 0;
    while (m0 >= g_off[e + 1]) e++;
    const __half* w1e = g_w1h + (size_t)e * FFN * DIM;
    const int n0 = blockIdx.y * BN;

    if (tid < BM) stok[tid] = g_slot_tok[m0 + tid];
    __syncthreads();

    uint32_t sb = (smem_u32(smem) + 127u) & ~127u;

    const __half* asrc[4]; const __half* bsrc[4];
    uint32_t dsto[4]; int asz[4];
#pragma unroll
    for (int i = 0; i < 4; i++) {
        int idx = tid + i * 256;
        int row = idx >> 3, ch = idx & 7;
        int tok = stok[row];
        asz[i]  = (tok < 0) ? 0 : 16;
        asrc[i] = g_xh + (size_t)((tok < 0) ? 0 : tok) * DIM + ch * 8;
        bsrc[i] = w1e + (size_t)(n0 + row) * DIM + ch * 8;
        dsto[i] = (uint32_t)row * 128 + ((uint32_t)(ch ^ (row & 7)) << 4);
    }

    Pre pre; pre_init(pre, tid);

    float c[4][4][4];
#pragma unroll
    for (int i = 0; i < 4; i++)
#pragma unroll
        for (int j = 0; j < 4; j++)
#pragma unroll
            for (int k = 0; k < 4; k++) c[i][j][k] = 0.0f;

    const int NK = DIM / BKF;   // 16
#pragma unroll
    for (int s = 0; s < 2; s++) {
        uint32_t ab = sb + s * STAGE_BYTES, bb = ab + TILE_BYTES;
#pragma unroll
        for (int i = 0; i < 4; i++) {
            cpa16(ab + dsto[i], asrc[i], asz[i]);
            cpa16(bb + dsto[i], bsrc[i], 16);
            asrc[i] += BKF; bsrc[i] += BKF;
        }
        cpa_commit();
    }

    for (int kt = 0; kt < NK; kt++) {
        int s = kt % NSTAGE;
        cpa_wait1();
        __syncthreads();
        if (kt + 2 < NK) {
            int sn = (kt + 2) % NSTAGE;
            uint32_t ab = sb + sn * STAGE_BYTES, bb = ab + TILE_BYTES;
#pragma unroll
            for (int i = 0; i < 4; i++) {
                cpa16(ab + dsto[i], asrc[i], asz[i]);
                cpa16(bb + dsto[i], bsrc[i], 16);
                asrc[i] += BKF; bsrc[i] += BKF;
            }
        }
        cpa_commit();
        compute_tile(pre, sb + s * STAGE_BYTES, c);
    }

    // epilogue: gelu -> fp16 h
    int lane = tid & 31, warp = tid >> 5;
    int wm = (warp >> 2) * 64, wn = (warp & 3) * 32;
    int g = lane >> 2, tg = lane & 3;
#pragma unroll
    for (int mt = 0; mt < 4; mt++) {
#pragma unroll
        for (int nt = 0; nt < 4; nt++) {
            int mb = m0 + wm + mt * 16 + g;
            int nb = n0 + wn + nt * 8 + tg * 2;
            __half2 v0 = __floats2half2_rn(gelu_exact(c[mt][nt][0]), gelu_exact(c[mt][nt][1]));
            __half2 v1 = __floats2half2_rn(gelu_exact(c[mt][nt][2]), gelu_exact(c[mt][nt][3]));
            *(__half2*)(g_hh + (size_t)mb * FFN + nb) = v0;
            *(__half2*)(g_hh + (size_t)(mb + 8) * FFN + nb) = v1;
        }
    }
}

// ---------------- GEMM2: out[tok] += w_slot * (h[slot] @ W2^T), atomic scatter ----------------
__global__ void __launch_bounds__(256, 2)
gemm2_p(float* __restrict__ out) {
    extern __shared__ char smem[];
    __shared__ int   stok[BM];
    __shared__ float swv[BM];

    const int tid = threadIdx.x;
    const int m0 = blockIdx.x * BM;
    if (m0 >= g_off[NEXP]) return;
    int e = 0;
    while (m0 >= g_off[e + 1]) e++;
    const __half* w2e = g_w2h + (size_t)e * DIM * FFN;
    const int n0 = blockIdx.y * BN;

    if (tid < BM) { stok[tid] = g_slot_tok[m0 + tid]; swv[tid] = g_slot_w[m0 + tid]; }
    __syncthreads();

    uint32_t sb = (smem_u32(smem) + 127u) & ~127u;

    const __half* asrc[4]; const __half* bsrc[4];
    uint32_t dsto[4];
#pragma unroll
    for (int i = 0; i < 4; i++) {
        int idx = tid + i * 256;
        int row = idx >> 3, ch = idx & 7;
        asrc[i] = g_hh + (size_t)(m0 + row) * FFN + ch * 8;
        bsrc[i] = w2e + (size_t)(n0 + row) * FFN + ch * 8;
        dsto[i] = (uint32_t)row * 128 + ((uint32_t)(ch ^ (row & 7)) << 4);
    }

    Pre pre; pre_init(pre, tid);

    float c[4][4][4];
#pragma unroll
    for (int i = 0; i < 4; i++)
#pragma unroll
        for (int j = 0; j < 4; j++)
#pragma unroll
            for (int k = 0; k < 4; k++) c[i][j][k] = 0.0f;

    const int NK = FFN / BKF;   // 64
#pragma unroll
    for (int s = 0; s < 2; s++) {
        uint32_t ab = sb + s * STAGE_BYTES, bb = ab + TILE_BYTES;
#pragma unroll
        for (int i = 0; i < 4; i++) {
            cpa16(ab + dsto[i], asrc[i], 16);
            cpa16(bb + dsto[i], bsrc[i], 16);
            asrc[i] += BKF; bsrc[i] += BKF;
        }
        cpa_commit();
    }

    for (int kt = 0; kt < NK; kt++) {
        int s = kt % NSTAGE;
        cpa_wait1();
        __syncthreads();
        if (kt + 2 < NK) {
            int sn = (kt + 2) % NSTAGE;
            uint32_t ab = sb + sn * STAGE_BYTES, bb = ab + TILE_BYTES;
#pragma unroll
            for (int i = 0; i < 4; i++) {
                cpa16(ab + dsto[i], asrc[i], 16);
                cpa16(bb + dsto[i], bsrc[i], 16);
                asrc[i] += BKF; bsrc[i] += BKF;
            }
        }
        cpa_commit();
        compute_tile(pre, sb + s * STAGE_BYTES, c);
    }

    // epilogue: scale + atomic scatter into out (combine fused; R9-proven cost-free)
    int lane = tid & 31, warp = tid >> 5;
    int wm = (warp >> 2) * 64, wn = (warp & 3) * 32;
    int g = lane >> 2, tg = lane & 3;
#pragma unroll
    for (int mt = 0; mt < 4; mt++) {
        int ml0 = wm + mt * 16 + g;
        int ml1 = ml0 + 8;
        int tok0 = stok[ml0], tok1 = stok[ml1];
        float w0 = swv[ml0], w1v = swv[ml1];
#pragma unroll
        for (int nt = 0; nt < 4; nt++) {
            int nb = n0 + wn + nt * 8 + tg * 2;
            if (tok0 >= 0) {
                atomicAdd(out + (size_t)tok0 * DIM + nb,     c[mt][nt][0] * w0);
                atomicAdd(out + (size_t)tok0 * DIM + nb + 1, c[mt][nt][1] * w0);
            }
            if (tok1 >= 0) {
                atomicAdd(out + (size_t)tok1 * DIM + nb,     c[mt][nt][2] * w1v);
                atomicAdd(out + (size_t)tok1 * DIM + nb + 1, c[mt][nt][3] * w1v);
            }
        }
    }
}

// ---------------- launcher: fork/join, combine fused into gemm2 ----------------
extern "C" void kernel_launch(void* const* d_in, const int* in_sizes, int n_in,
                              void* d_out, int out_size) {
    const float* x  = (const float*)d_in[0];
    const float* rw = (const float*)d_in[1];
    const float* w1 = (const float*)d_in[2];
    const float* w2 = (const float*)d_in[3];
    float* out = (float*)d_out;

    static int configured = 0;
    static cudaStream_t s1, s2;
    static cudaEvent_t evRoot, evRoute, evW2;
    if (!configured) {
        cudaFuncSetAttribute(gemm1_p, cudaFuncAttributeMaxDynamicSharedMemorySize, SMEM_TOTAL);
        cudaFuncSetAttribute(gemm2_p, cudaFuncAttributeMaxDynamicSharedMemorySize, SMEM_TOTAL);
        cudaStreamCreateWithFlags(&s1, cudaStreamNonBlocking);
        cudaStreamCreateWithFlags(&s2, cudaStreamNonBlocking);
        cudaEventCreateWithFlags(&evRoot, cudaEventDisableTiming);
        cudaEventCreateWithFlags(&evRoute, cudaEventDisableTiming);
        cudaEventCreateWithFlags(&evW2, cudaEventDisableTiming);
        configured = 1;
    }

    const int n8x   = NUM_TOK * DIM / 8;
    const int n8w1  = NEXP * FFN * DIM / 8;
    const int n8w2  = NEXP * DIM * FFN / 8;
    const int n8xw1 = n8x + n8w1;

    // fork s1 (routing chain) and s2 (w2 conversion + out zeroing)
    cudaEventRecord(evRoot, 0);
    cudaStreamWaitEvent(s1, evRoot, 0);
    cudaStreamWaitEvent(s2, evRoot, 0);

    // main stream: x + w1 -> fp16 (gemm1 prerequisite)
    prep_xw1_kernel<<<(n8xw1 + 255) / 256, 256>>>((const float4*)x, (const float4*)w1);

    // s1: counters -> router -> offsets -> place
    init_small_kernel<<<1, 32, 0, s1>>>();
    router_kernel<<<NUM_TOK / 8, 256, 0, s1>>>(x, rw);
    offsets_kernel<<<1, 32, 0, s1>>>();
    place_kernel<<<32, 256, 0, s1>>>();
    cudaEventRecord(evRoute, s1);

    // s2: w2 -> fp16 + zero out (both gemm2 prerequisites; overlap gemm1)
    prep_w2_kernel<<<(n8w2 + 255) / 256, 256, 0, s2>>>((const float4*)w2);
    zero_out_kernel<<<(out_size / 4 + 255) / 256, 256, 0, s2>>>((float4*)out, out_size / 4);
    cudaEventRecord(evW2, s2);

    // join routing, run gemm1
    cudaStreamWaitEvent(0, evRoute, 0);
    gemm1_p<<<dim3(MAX_MTILES, FFN / BN), 256, SMEM_TOTAL>>>();

    // join w2+zero, run gemm2 (writes final out via atomic scatter)
    cudaStreamWaitEvent(0, evW2, 0);
    gemm2_p<<<dim3(MAX_MTILES, DIM / BN), 256, SMEM_TOTAL>>>(out);
}